// round 1
// baseline (speedup 1.0000x reference)
#include <cuda_runtime.h>
#include <math_constants.h>

// BarycentricPooling — closed form.
//
// The reference's final sinkhorn update computes
//   g[n,k] = -EPS * logsumexp_s(log_a + (f[n,s]-C[n,s,k])/EPS)
// and then reads the transport plan's second marginal
//   hist[n,k] = exp( g/EPS + log_b + logsumexp_s(log_a + (f-C)/EPS) )
//             = exp( log_b[k] )            (the lse term is -g/EPS by definition)
// so hist == softmax(log_prior) for every n, the segment mean of identical
// rows is that row, and the empty-graph fallback is the same value.
// Output [B,K] = softmax(log_codebook_prior) broadcast over rows.

__global__ void prior_broadcast_kernel(const float* __restrict__ log_prior,
                                       float* __restrict__ out,
                                       int K, int total) {
    extern __shared__ float soft[];   // K floats
    int tid = threadIdx.x;

    // Every block independently computes the K-way softmax (K=64: trivial).
    if (tid < K) {
        float m = -CUDART_INF_F;
        #pragma unroll 4
        for (int j = 0; j < K; ++j) m = fmaxf(m, log_prior[j]);
        float s = 0.0f;
        #pragma unroll 4
        for (int j = 0; j < K; ++j) s += expf(log_prior[j] - m);
        soft[tid] = expf(log_prior[tid] - m) / s;
    }
    __syncthreads();

    // Broadcast: out[b*K + k] = soft[k]; row-major so k = i % K.
    for (int i = blockIdx.x * blockDim.x + tid; i < total;
         i += gridDim.x * blockDim.x) {
        out[i] = soft[i % K];
    }
}

extern "C" void kernel_launch(void* const* d_in, const int* in_sizes, int n_in,
                              void* d_out, int out_size) {
    // metadata order: node_distributions, batch_idx, codebook, log_codebook_prior
    const float* log_prior = (const float*)d_in[3];
    const int K = in_sizes[3];          // 64
    float* out = (float*)d_out;         // [B, K] = out_size floats

    const int threads = 256;
    int blocks = (out_size + threads - 1) / threads;
    if (blocks > 64) blocks = 64;
    if (blocks < 1) blocks = 1;
    size_t shmem = (size_t)K * sizeof(float);
    prior_broadcast_kernel<<<blocks, threads, shmem>>>(log_prior, out, K, out_size);
}

// round 2
// speedup vs baseline: 1.1192x; 1.1192x over previous
#include <cuda_runtime.h>
#include <math_constants.h>

// BarycentricPooling — closed form (see R1 derivation):
// After the final g-half-step, the transport plan's second marginal equals
// b = softmax(log_prior) exactly, so hist[n,:] == b for all n, the segment
// mean of identical rows is b, and the empty-graph fallback is also b.
// Output [B=256, K=64] = softmax(log_codebook_prior) broadcast over rows.
//
// R2: warp-cooperative softmax (2 vals/lane + butterfly shuffles, __expf),
// float4 broadcast stores. One thread = one 16B store.

__global__ void prior_broadcast_kernel(const float* __restrict__ log_prior,
                                       float4* __restrict__ out4,
                                       int total4) {
    __shared__ float soft[64];
    const int tid = threadIdx.x;

    if (tid < 32) {
        // K = 64: two values per lane.
        float v0 = log_prior[tid];
        float v1 = log_prior[tid + 32];
        float m = fmaxf(v0, v1);
        #pragma unroll
        for (int o = 16; o > 0; o >>= 1)
            m = fmaxf(m, __shfl_xor_sync(0xffffffff, m, o));
        float e0 = __expf(v0 - m);
        float e1 = __expf(v1 - m);
        float s = e0 + e1;
        #pragma unroll
        for (int o = 16; o > 0; o >>= 1)
            s += __shfl_xor_sync(0xffffffff, s, o);
        float inv = 1.0f / s;
        soft[tid]      = e0 * inv;
        soft[tid + 32] = e1 * inv;
    }
    __syncthreads();

    // K=64 floats = 16 float4s per row; row-major broadcast.
    const float4* s4 = reinterpret_cast<const float4*>(soft);
    for (int i = blockIdx.x * blockDim.x + tid; i < total4;
         i += gridDim.x * blockDim.x) {
        out4[i] = s4[i & 15];
    }
}

// Generic fallback (any K), scalar — only used if K != 64 or out_size % 4 != 0.
__global__ void prior_broadcast_generic(const float* __restrict__ log_prior,
                                        float* __restrict__ out,
                                        int K, int total) {
    extern __shared__ float soft[];
    const int tid = threadIdx.x;
    if (tid < K) {
        float m = -CUDART_INF_F;
        for (int j = 0; j < K; ++j) m = fmaxf(m, log_prior[j]);
        float s = 0.0f;
        for (int j = 0; j < K; ++j) s += __expf(log_prior[j] - m);
        soft[tid] = __expf(log_prior[tid] - m) / s;
    }
    __syncthreads();
    for (int i = blockIdx.x * blockDim.x + tid; i < total;
         i += gridDim.x * blockDim.x)
        out[i] = soft[i % K];
}

extern "C" void kernel_launch(void* const* d_in, const int* in_sizes, int n_in,
                              void* d_out, int out_size) {
    // metadata order: node_distributions, batch_idx, codebook, log_codebook_prior
    const float* log_prior = (const float*)d_in[3];
    const int K = in_sizes[3];  // 64

    if (K == 64 && (out_size & 3) == 0) {
        int total4 = out_size >> 2;             // 4096 float4s
        const int threads = 128;
        int blocks = (total4 + threads - 1) / threads;  // 32
        prior_broadcast_kernel<<<blocks, threads>>>(
            log_prior, (float4*)d_out, total4);
    } else {
        const int threads = 256;
        int blocks = (out_size + threads - 1) / threads;
        if (blocks > 64) blocks = 64;
        if (blocks < 1) blocks = 1;
        prior_broadcast_generic<<<blocks, threads, (size_t)K * sizeof(float)>>>(
            log_prior, (float*)d_out, K, out_size);
    }
}

// round 3
// speedup vs baseline: 1.4694x; 1.3129x over previous
#include <cuda_runtime.h>
#include <math_constants.h>

// BarycentricPooling — closed form (R1 derivation):
// After the final g-half-step the transport plan's second marginal equals
// b = softmax(log_prior) exactly; hist[n,:] == b for all n, segment-mean of
// identical rows is b, empty-graph fallback is b.
// Output [B=256, K=64] = softmax(log_codebook_prior) broadcast over rows.
//
// R3: fully warp-local — no smem, no __syncthreads. Each warp redundantly
// computes the 64-way softmax from one LDG.64 per lane + butterfly shuffles,
// then each thread emits one STG.128 gathered via 4 index shuffles.

__global__ void __launch_bounds__(128, 1)
prior_broadcast_kernel(const float2* __restrict__ lp2,
                       float4* __restrict__ out4,
                       int total4) {
    const int lane = threadIdx.x & 31;

    // soft[c] will live at lane c/2: s0 = soft[2*lane], s1 = soft[2*lane+1]
    float2 v = lp2[lane];                       // one LDG.64, lanes cover K=64
    float m = fmaxf(v.x, v.y);
    #pragma unroll
    for (int o = 16; o > 0; o >>= 1)
        m = fmaxf(m, __shfl_xor_sync(0xffffffff, m, o));
    float e0 = __expf(v.x - m);
    float e1 = __expf(v.y - m);
    float s = e0 + e1;
    #pragma unroll
    for (int o = 16; o > 0; o >>= 1)
        s += __shfl_xor_sync(0xffffffff, s, o);
    float inv = __frcp_rn(s);
    float s0 = e0 * inv;
    float s1 = e1 * inv;

    // Output float4 index i covers soft[4j .. 4j+3], j = i & 15.
    int i = blockIdx.x * blockDim.x + threadIdx.x;
    int j = i & 15;
    float4 w;
    w.x = __shfl_sync(0xffffffff, s0, 2 * j);
    w.y = __shfl_sync(0xffffffff, s1, 2 * j);
    w.z = __shfl_sync(0xffffffff, s0, 2 * j + 1);
    w.w = __shfl_sync(0xffffffff, s1, 2 * j + 1);
    if (i < total4) out4[i] = w;
}

// Generic fallback (any K) — never taken for this problem shape.
__global__ void prior_broadcast_generic(const float* __restrict__ log_prior,
                                        float* __restrict__ out,
                                        int K, int total) {
    extern __shared__ float soft[];
    const int tid = threadIdx.x;
    if (tid < K) {
        float m = -CUDART_INF_F;
        for (int j = 0; j < K; ++j) m = fmaxf(m, log_prior[j]);
        float s = 0.0f;
        for (int j = 0; j < K; ++j) s += __expf(log_prior[j] - m);
        soft[tid] = __expf(log_prior[tid] - m) / s;
    }
    __syncthreads();
    for (int i = blockIdx.x * blockDim.x + tid; i < total;
         i += gridDim.x * blockDim.x)
        out[i] = soft[i % K];
}

extern "C" void kernel_launch(void* const* d_in, const int* in_sizes, int n_in,
                              void* d_out, int out_size) {
    // metadata order: node_distributions, batch_idx, codebook, log_codebook_prior
    const float* log_prior = (const float*)d_in[3];
    const int K = in_sizes[3];  // 64

    if (K == 64 && (out_size & 3) == 0) {
        int total4 = out_size >> 2;                     // 4096
        const int threads = 128;
        int blocks = (total4 + threads - 1) / threads;  // 32
        prior_broadcast_kernel<<<blocks, threads>>>(
            (const float2*)log_prior, (float4*)d_out, total4);
    } else {
        const int threads = 256;
        int blocks = (out_size + threads - 1) / threads;
        if (blocks > 64) blocks = 64;
        if (blocks < 1) blocks = 1;
        prior_broadcast_generic<<<blocks, threads, (size_t)K * sizeof(float)>>>(
            log_prior, (float*)d_out, K, out_size);
    }
}